// round 17
// baseline (speedup 1.0000x reference)
#include <cuda_runtime.h>

// Random_RNN two-hop — algebraic collapse: out = (W2*W1) * x^T.
// NEW SPLIT: fold inlined into the scan (no second bucket, no fold kernel).
//   k1: xT transpose + hop1 buckets (j -> {s,w1}) + zero M.       (small)
//   k2: pinned 1184x256 int4 scan of a_dst; each hit edge (j,o,w2)
//       immediately REDs w2*w1 over j's in-edge row into dense M.
//   k3: gemm out = M * xT, + reset g_c1 for the next launch/replay.
// Lessons pinned: in-kernel grid sync ALWAYS loses to a launch boundary
// (R9/R13/R16); scan shape 1184x256 flat is optimal (R14/R15); counters one
// per 128B L2 line (R8). REDs are fire-and-forget -> no result stall.

#define B      128
#define IN_F   256
#define N_ASS  4096
#define OUT_F  256
#define ASS0   256
#define OUT0   (IN_F + N_ASS)   // 4352
#define CAP1   40               // per-j in-degree (E 12.8, sd 3.5, max ~26)
#define XT_N   (IN_F * B)       // 32768
#define MSZ    (OUT_F * IN_F)   // 65536
#define CSTR   32               // counter stride: 32 ints = 128B = 1 L2 line

__device__ float2 g_b1[N_ASS * CAP1];   // in-edges of j: {s (int bits), w1}
__device__ int    g_c1[N_ASS * CSTR];   // one counter per L2 line
__device__ float  g_xT[IN_F * B];       // x transposed [s][b]
__device__ float  g_M[MSZ];             // dense W2*W1, [o][s]

// ---------------------------------------------------------------- k1: prep
// xT transpose + hop1 buckets + zero M.  ~117K items over 131K threads.
__global__ void __launch_bounds__(256)
k_prep(const float* __restrict__ x,
       const int* __restrict__ in_src, const int* __restrict__ in_dst,
       const float* __restrict__ in_w, int E_in) {
    const int i  = blockIdx.x * 256 + threadIdx.x;
    const int nt = gridDim.x * 256;

    for (int m = i; m < MSZ; m += nt) g_M[m] = 0.f;

    for (int idx = i; idx < XT_N; idx += nt) {         // x[B][IN_F]->xT[IN_F][B]
        int b = idx >> 8, s = idx & 255;               // IN_F == 256
        g_xT[s * B + b] = x[idx];
    }

    for (int e = i; e < E_in; e += nt) {               // hop1 edges (~52K)
        int   j = in_dst[e] - ASS0;
        int   s = in_src[e];
        float w = in_w[e];
        int pos = atomicAdd(&g_c1[j * CSTR], 1);
        g_b1[j * CAP1 + pos] = make_float2(__int_as_float(s), w);
    }
}

// ---------------------------------------------------------------- k2: scan+fold
// Pinned scan shape. Per hit edge: read j's in-edge row, RED products into M.
__global__ void __launch_bounds__(256, 8)
k_scanfold(const int* __restrict__ a_src, const int* __restrict__ a_dst,
           const float* __restrict__ a_w, int E_ass) {
    const int i  = blockIdx.x * 256 + threadIdx.x;
    const int nt = gridDim.x * 256;                    // 303104

    const int     E4  = E_ass >> 2;
    const int4*   a4  = (const int4*)a_dst;
    const int4*   s4p = (const int4*)a_src;
    const float4* w4p = (const float4*)a_w;
    for (int q = i; q < E4; q += nt) {
        int4 d4 = __ldg(&a4[q]);
        if (d4.x >= OUT0 || d4.y >= OUT0 || d4.z >= OUT0 || d4.w >= OUT0) {
            int4   s4 = __ldg(&s4p[q]);                // conditional side loads
            float4 w4 = __ldg(&w4p[q]);
            int   dd[4] = {d4.x, d4.y, d4.z, d4.w};
            int   ss[4] = {s4.x, s4.y, s4.z, s4.w};
            float ww[4] = {w4.x, w4.y, w4.z, w4.w};
#pragma unroll
            for (int m = 0; m < 4; m++) {
                if (dd[m] >= OUT0) {
                    int   j  = ss[m] - ASS0;
                    int   o  = dd[m] - OUT0;
                    float w2 = ww[m];
                    int   n1 = __ldg(&g_c1[j * CSTR]); // L2-hot
                    const float2* e1 = &g_b1[j * CAP1];
                    float* Mrow = &g_M[o * IN_F];
                    for (int k = 0; k < n1; k += 4) {  // 4-wide predicated
                        float2 p[4];
#pragma unroll
                        for (int u = 0; u < 4; u++)
                            p[u] = (k + u < n1) ? __ldg(&e1[k + u])
                                                : make_float2(0.f, 0.f);
#pragma unroll
                        for (int u = 0; u < 4; u++)
                            if (k + u < n1)
                                atomicAdd(&Mrow[__float_as_int(p[u].x)],
                                          p[u].y * w2);   // RED: no stall
                    }
                }
            }
        }
    }
    for (int e = (E4 << 2) + i; e < E_ass; e += nt) {  // tail (E_ass % 4)
        int d = a_dst[e];
        if (d >= OUT0) {
            int   j  = a_src[e] - ASS0;
            int   o  = d - OUT0;
            float w2 = a_w[e];
            int   n1 = __ldg(&g_c1[j * CSTR]);
            const float2* e1 = &g_b1[j * CAP1];
            for (int k = 0; k < n1; k++) {
                float2 p = __ldg(&e1[k]);
                atomicAdd(&g_M[o * IN_F + __float_as_int(p.x)], p.y * w2);
            }
        }
    }
}

// ---------------------------------------------------------------- k3: gemm
// out[b][o] = sum_s M[o][s] * xT[s][b]; block o; 4 s-groups x 128 b-threads.
// Also resets this block's 16 hop1 counters (sole post-fold touch).
__global__ void __launch_bounds__(512) k_gemm(float* __restrict__ out) {
    __shared__ float sM[IN_F];
    __shared__ float part[3][B];
    int o = blockIdx.x;
    int tid = threadIdx.x;
    if (tid < 16) g_c1[(o * 16 + tid) * CSTR] = 0;     // 256 blocks x 16 = 4096
    for (int s = tid; s < IN_F; s += 512) sM[s] = g_M[o * IN_F + s];
    __syncthreads();
    int g = tid >> 7, b = tid & 127;
    float r = 0.f;
    int s0 = g * 64;
#pragma unroll
    for (int sr = 0; sr < 64; sr += 8) {               // 8 independent loads
        float v[8];
#pragma unroll
        for (int k = 0; k < 8; k++)
            v[k] = g_xT[(s0 + sr + k) * B + b];
#pragma unroll
        for (int k = 0; k < 8; k++)
            r += sM[s0 + sr + k] * v[k];
    }
    if (g > 0) part[g - 1][b] = r;
    __syncthreads();
    if (g == 0)
        out[b * OUT_F + o] = r + part[0][b] + part[1][b] + part[2][b];
}

// ---------------------------------------------------------------- launch
extern "C" void kernel_launch(void* const* d_in, const int* in_sizes, int n_in,
                              void* d_out, int out_size) {
    const float* x      = (const float*)d_in[0];
    const float* in_w   = (const float*)d_in[1];
    const float* a_w    = (const float*)d_in[2];
    const int*   in_src = (const int*)d_in[3];
    const int*   in_dst = (const int*)d_in[4];
    const int*   a_src  = (const int*)d_in[5];
    const int*   a_dst  = (const int*)d_in[6];
    int E_in  = in_sizes[1];
    int E_ass = in_sizes[2];
    float* out = (float*)d_out;

    k_prep    <<<512, 256>>>(x, in_src, in_dst, in_w, E_in);
    k_scanfold<<<1184, 256>>>(a_src, a_dst, a_w, E_ass);
    k_gemm    <<<OUT_F, 512>>>(out);
}